// round 2
// baseline (speedup 1.0000x reference)
#include <cuda_runtime.h>
#include <math.h>

#define NN 2048
#define NE 4096
#define DD 128
#define DKV 384
#define NHEAD 4
#define DHEAD 32
#define NK 819     /* int(0.4*2048) */
#define EK 1638    /* int(0.4*4096) */
#define MAXC 512

// ---------------- scratch (device globals; no allocation allowed) ----------------
__device__ float g_nscore[NN];
__device__ float g_escore[NE];
__device__ int   g_nmask[NN];
__device__ int   g_etop[NE];
__device__ int   g_emask[NE];
__device__ int   g_deg[NN];
__device__ int   g_rowstart[NN + 1];
__device__ int   g_cursor[NN];
__device__ int   g_inc[2 * NE];
__device__ float g_kvin[NE * DKV];   // [wef | nf[src] | nf[dst]]
__device__ float g_q[NE * DD];
__device__ float g_k[NE * DD];
__device__ float g_v[NE * DD];
__device__ float g_ctx[NE * DD];
__device__ float g_upd[NE * DD];
__device__ float g_hid[NE * DD];

__device__ __forceinline__ float* gbuf(int id) {
    switch (id) {
        case 0: return g_kvin;
        case 1: return g_q;
        case 2: return g_k;
        case 3: return g_v;
        case 4: return g_ctx;
        case 5: return g_upd;
        default: return g_hid;
    }
}

__device__ __forceinline__ float wsum(float v) {
    v += __shfl_xor_sync(0xffffffffu, v, 16);
    v += __shfl_xor_sync(0xffffffffu, v, 8);
    v += __shfl_xor_sync(0xffffffffu, v, 4);
    v += __shfl_xor_sync(0xffffffffu, v, 2);
    v += __shfl_xor_sync(0xffffffffu, v, 1);
    return v;
}
__device__ __forceinline__ float wmax(float v) {
    v = fmaxf(v, __shfl_xor_sync(0xffffffffu, v, 16));
    v = fmaxf(v, __shfl_xor_sync(0xffffffffu, v, 8));
    v = fmaxf(v, __shfl_xor_sync(0xffffffffu, v, 4));
    v = fmaxf(v, __shfl_xor_sync(0xffffffffu, v, 2));
    v = fmaxf(v, __shfl_xor_sync(0xffffffffu, v, 1));
    return v;
}
__device__ __forceinline__ int wsumi(int v) {
    v += __shfl_xor_sync(0xffffffffu, v, 16);
    v += __shfl_xor_sync(0xffffffffu, v, 8);
    v += __shfl_xor_sync(0xffffffffu, v, 4);
    v += __shfl_xor_sync(0xffffffffu, v, 2);
    v += __shfl_xor_sync(0xffffffffu, v, 1);
    return v;
}

// ---------------- kernels ----------------

__global__ void k_zero() {
    int i = blockIdx.x * blockDim.x + threadIdx.x;
    if (i < NN) g_deg[i] = 0;
}

// warp per row: importance scores (node + edge)
__global__ __launch_bounds__(256) void k_scores(
    const float* __restrict__ nf, const float* __restrict__ ef,
    const float* __restrict__ wn, const float* __restrict__ we)
{
    int gw = blockIdx.x * 8 + (threadIdx.x >> 5);
    int lane = threadIdx.x & 31;
    const float* base;
    const float* w;
    if (gw < NN) { base = nf + (size_t)gw * DD; w = wn; }
    else         { base = ef + (size_t)(gw - NN) * DD; w = we; }
    float s = 0.f;
#pragma unroll
    for (int l = 0; l < 4; l++) {
        int d = lane + l * 32;
        s += base[d] * w[d];
    }
    s = wsum(s);
    if (lane == 0) {
        if (gw < NN) g_nscore[gw] = s;
        else         g_escore[gw - NN] = s;
    }
}

// warp per row: exact top-k membership by rank counting (values assumed distinct)
__global__ __launch_bounds__(256) void k_masks() {
    int gw = blockIdx.x * 8 + (threadIdx.x >> 5);
    int lane = threadIdx.x & 31;
    if (gw < NN) {
        float s = g_nscore[gw];
        int c = 0;
        for (int j = lane; j < NN; j += 32) c += (g_nscore[j] > s);
        c = wsumi(c);
        if (lane == 0) g_nmask[gw] = (c < NK);
    } else {
        int e = gw - NN;
        float s = g_escore[e];
        int c = 0;
        for (int j = lane; j < NE; j += 32) c += (g_escore[j] > s);
        c = wsumi(c);
        if (lane == 0) g_etop[e] = (c < EK);
    }
}

__global__ void k_edge_deg(const int* __restrict__ ei) {
    int e = blockIdx.x * blockDim.x + threadIdx.x;
    if (e >= NE) return;
    int s = ei[e], d = ei[NE + e];
    g_emask[e] = (g_etop[e] && g_nmask[s] && g_nmask[d]) ? 1 : 0;
    atomicAdd(&g_deg[s], 1);
    if (d != s) atomicAdd(&g_deg[d], 1);
}

// single-block exclusive scan of degrees (2048 elems, 1024 threads, pair + Hillis-Steele)
__global__ void k_scan() {
    __shared__ int ps[1024];
    int t = threadIdx.x;
    int a = g_deg[2 * t];
    int b = g_deg[2 * t + 1];
    ps[t] = a + b;
    __syncthreads();
    for (int off = 1; off < 1024; off <<= 1) {
        int v = ps[t];
        if (t >= off) v += ps[t - off];
        __syncthreads();
        ps[t] = v;
        __syncthreads();
    }
    int excl = (t == 0) ? 0 : ps[t - 1];
    g_rowstart[2 * t] = excl;
    g_rowstart[2 * t + 1] = excl + a;
    g_cursor[2 * t] = excl;
    g_cursor[2 * t + 1] = excl + a;
    if (t == 1023) g_rowstart[NN] = ps[1023];
}

__global__ void k_fill(const int* __restrict__ ei) {
    int e = blockIdx.x * blockDim.x + threadIdx.x;
    if (e >= NE) return;
    int s = ei[e], d = ei[NE + e];
    int p = atomicAdd(&g_cursor[s], 1);
    g_inc[p] = e;
    if (d != s) {
        p = atomicAdd(&g_cursor[d], 1);
        g_inc[p] = e;
    }
}

// build kv_in = [wef | nf[src] | nf[dst]], block per edge
__global__ __launch_bounds__(128) void k_kvin(
    const float* __restrict__ nf, const float* __restrict__ ef,
    const int* __restrict__ ei)
{
    int e = blockIdx.x;
    int t = threadIdx.x;
    int s = ei[e], d = ei[NE + e];
    float m = g_emask[e] ? 1.f : 0.f;
    g_kvin[(size_t)e * DKV + t]          = ef[(size_t)e * DD + t] * m;
    g_kvin[(size_t)e * DKV + DD + t]     = nf[(size_t)s * DD + t];
    g_kvin[(size_t)e * DKV + 2 * DD + t] = nf[(size_t)d * DD + t];
}

// generic fp32 SGEMM: C[4096 x 128] = A[4096 x kdim] @ B[kdim x 128] + bias
// blockIdx.y selects (B0,bias0,C0) or (B1,bias1,C1) so K/V share a launch.
// Optional residual (strided) and tanh-GELU epilogue.
__global__ __launch_bounds__(256) void k_gemm(
    int a_id, int lda,
    const float* __restrict__ B0, const float* __restrict__ B1,
    const float* __restrict__ bias0, const float* __restrict__ bias1,
    int c0_id, int c1_id, int kdim,
    int resid_id, int rlda, int dogelu)
{
    __shared__ float Ast[16 * 65];               // A^T tile [kk][row], padded
    __shared__ __align__(16) float Bs[16 * 128]; // B tile [kk][col]
    const float* A    = gbuf(a_id);
    const float* B    = (blockIdx.y == 0) ? B0 : B1;
    const float* bias = (blockIdx.y == 0) ? bias0 : bias1;
    float* C          = gbuf((blockIdx.y == 0) ? c0_id : c1_id);

    int tid = threadIdx.x;
    int rb = blockIdx.x * 64;
    int ty = tid >> 4, tx = tid & 15;

    float acc[4][8];
#pragma unroll
    for (int i = 0; i < 4; i++)
#pragma unroll
        for (int j = 0; j < 8; j++) acc[i][j] = 0.f;

    for (int k0 = 0; k0 < kdim; k0 += 16) {
#pragma unroll
        for (int l = 0; l < 4; l++) {
            int idx = tid + l * 256;
            int r = idx >> 4, kk = idx & 15;
            Ast[kk * 65 + r] = A[(size_t)(rb + r) * lda + k0 + kk];
        }
#pragma unroll
        for (int l = 0; l < 8; l++) {
            int idx = tid + l * 256;
            int kk = idx >> 7, c = idx & 127;
            Bs[kk * 128 + c] = B[(size_t)(k0 + kk) * DD + c];
        }
        __syncthreads();
#pragma unroll
        for (int kk = 0; kk < 16; kk++) {
            float a0 = Ast[kk * 65 + ty * 4 + 0];
            float a1 = Ast[kk * 65 + ty * 4 + 1];
            float a2 = Ast[kk * 65 + ty * 4 + 2];
            float a3 = Ast[kk * 65 + ty * 4 + 3];
            float4 bx = *(const float4*)&Bs[kk * 128 + tx * 8];
            float4 by = *(const float4*)&Bs[kk * 128 + tx * 8 + 4];
            float bv[8] = {bx.x, bx.y, bx.z, bx.w, by.x, by.y, by.z, by.w};
#pragma unroll
            for (int j = 0; j < 8; j++) {
                acc[0][j] += a0 * bv[j];
                acc[1][j] += a1 * bv[j];
                acc[2][j] += a2 * bv[j];
                acc[3][j] += a3 * bv[j];
            }
        }
        __syncthreads();
    }

    const float* R = (resid_id >= 0) ? gbuf(resid_id) : nullptr;
#pragma unroll
    for (int i = 0; i < 4; i++) {
        int row = rb + ty * 4 + i;
#pragma unroll
        for (int j = 0; j < 8; j++) {
            int col = tx * 8 + j;
            float v = acc[i][j] + bias[col];
            if (R) v += R[(size_t)row * rlda + col];
            if (dogelu) {
                float x = v;
                v = 0.5f * x * (1.f + tanhf(0.7978845608028654f * (x + 0.044715f * x * x * x)));
            }
            C[(size_t)row * DD + col] = v;
        }
    }
}

// sparse edge attention: block per query edge, warp per head.
// Candidate set = edges sharing an endpoint with e (exactly the adjacency mask).
// Masked entries contribute exactly 0 in the fp32 reference (exp(-1e9-m) underflows),
// so sparse softmax over candidates is equivalent.
__global__ __launch_bounds__(128) void k_attn(const int* __restrict__ ei) {
    __shared__ int cand[MAXC];
    __shared__ int s_nc;
    __shared__ float sc[NHEAD][MAXC];
    int e = blockIdx.x;
    int tid = threadIdx.x;
    int qs = ei[e], qd = ei[NE + e];
    if (tid == 0) {
        int n = 0;
        for (int p = g_rowstart[qs]; p < g_rowstart[qs + 1] && n < MAXC; p++) cand[n++] = g_inc[p];
        if (qd != qs) {
            for (int p = g_rowstart[qd]; p < g_rowstart[qd + 1] && n < MAXC; p++) {
                int f = g_inc[p];
                int fs = ei[f], fd = ei[NE + f];
                if (fs != qs && fd != qs) cand[n++] = f;  // dedupe vs inc[qs]
            }
        }
        s_nc = n;
    }
    __syncthreads();
    int nc = s_nc;
    int h = tid >> 5, lane = tid & 31;
    float qv = g_q[(size_t)e * DD + h * DHEAD + lane];
    const float scale = 0.17677669529663687f; // 1/sqrt(32)
    for (int c = 0; c < nc; c++) {
        int f = cand[c];
        float t = qv * g_k[(size_t)f * DD + h * DHEAD + lane];
        t = wsum(t);
        if (lane == 0) sc[h][c] = t * scale;
    }
    __syncwarp();
    float m = -1e30f;
    for (int c = lane; c < nc; c += 32) m = fmaxf(m, sc[h][c]);
    m = wmax(m);
    float l = 0.f;
    for (int c = lane; c < nc; c += 32) {
        float p = expf(sc[h][c] - m);
        sc[h][c] = p;
        l += p;
    }
    l = wsum(l);
    __syncwarp();
    float acc = 0.f;
    for (int c = 0; c < nc; c++)
        acc += sc[h][c] * g_v[(size_t)cand[c] * DD + h * DHEAD + lane];
    g_ctx[(size_t)e * DD + h * DHEAD + lane] = acc / l;
}

// out[e, 0..3] = h[e] @ W2 + b2, warp per edge
__global__ __launch_bounds__(256) void k_final(
    const float* __restrict__ W2, const float* __restrict__ b2,
    float* __restrict__ out)
{
    int gw = blockIdx.x * 8 + (threadIdx.x >> 5);
    int lane = threadIdx.x & 31;
    if (gw >= NE) return;
    float a0 = 0.f, a1 = 0.f, a2 = 0.f, a3 = 0.f;
    for (int k = lane; k < DD; k += 32) {
        float hv = g_hid[(size_t)gw * DD + k];
        float4 w = *(const float4*)&W2[k * 4];
        a0 += hv * w.x;
        a1 += hv * w.y;
        a2 += hv * w.z;
        a3 += hv * w.w;
    }
    a0 = wsum(a0);
    a1 = wsum(a1);
    a2 = wsum(a2);
    a3 = wsum(a3);
    if (lane == 0) {
        out[gw * 4 + 0] = a0 + b2[0];
        out[gw * 4 + 1] = a1 + b2[1];
        out[gw * 4 + 2] = a2 + b2[2];
        out[gw * 4 + 3] = a3 + b2[3];
    }
}

// ---------------- launch ----------------
extern "C" void kernel_launch(void* const* d_in, const int* in_sizes, int n_in,
                              void* d_out, int out_size) {
    const float* nf = (const float*)d_in[0];
    const float* ef = (const float*)d_in[1];
    const int*   ei = (const int*)d_in[2];
    const float* wn = (const float*)d_in[3];
    const float* we = (const float*)d_in[4];
    const float* Wq = (const float*)d_in[5];
    const float* bq = (const float*)d_in[6];
    const float* Wk = (const float*)d_in[7];
    const float* bk = (const float*)d_in[8];
    const float* Wv = (const float*)d_in[9];
    const float* bv = (const float*)d_in[10];
    const float* Wo = (const float*)d_in[11];
    const float* bo = (const float*)d_in[12];
    const float* W1 = (const float*)d_in[13];
    const float* b1 = (const float*)d_in[14];
    const float* W2 = (const float*)d_in[15];
    const float* b2 = (const float*)d_in[16];
    float* out = (float*)d_out;

    k_zero<<<8, 256>>>();
    k_scores<<<768, 256>>>(nf, ef, wn, we);
    k_masks<<<768, 256>>>();
    k_edge_deg<<<16, 256>>>(ei);
    k_scan<<<1, 1024>>>();
    k_fill<<<16, 256>>>(ei);
    k_kvin<<<4096, 128>>>(nf, ef, ei);
    // Q = wef @ Wq + bq   (wef = first 128 cols of kv_in, lda=384)
    k_gemm<<<dim3(64, 1), 256>>>(0, DKV, Wq, Wq, bq, bq, 1, 1, 128, -1, 0, 0);
    // K,V = kv_in @ {Wk,Wv} + {bk,bv}  (fused in one launch via blockIdx.y)
    k_gemm<<<dim3(64, 2), 256>>>(0, DKV, Wk, Wv, bk, bv, 2, 3, DKV, -1, 0, 0);
    k_attn<<<4096, 128>>>(ei);
    // upd = ctx @ Wo + bo + wef (residual from kv_in with stride 384)
    k_gemm<<<dim3(64, 1), 256>>>(4, DD, Wo, Wo, bo, bo, 5, 5, 128, 0, DKV, 0);
    // hid = gelu(upd @ W1 + b1)
    k_gemm<<<dim3(64, 1), 256>>>(5, DD, W1, W1, b1, b1, 6, 6, 128, -1, 0, 1);
    k_final<<<512, 256>>>(W2, b2, out);
}